// round 2
// baseline (speedup 1.0000x reference)
#include <cuda_runtime.h>
#include <math.h>

// Problem constants
#define Bc   512
#define NAc  128
#define NLc  512
#define Dc   128
#define KAc  16
#define KLc  16
#define NNODES 32   // KA + KL

// ---------------------------------------------------------------------------
// f32x2 helpers (Blackwell packed fp32 FMA)
// ---------------------------------------------------------------------------
__device__ __forceinline__ unsigned long long pk2(float lo, float hi) {
    unsigned long long r;
    asm("mov.b64 %0, {%1, %2};" : "=l"(r) : "f"(lo), "f"(hi));
    return r;
}
__device__ __forceinline__ void fma2(unsigned long long& d,
                                     unsigned long long a,
                                     unsigned long long b) {
    asm("fma.rn.f32x2 %0, %1, %2, %0;" : "+l"(d) : "l"(a), "l"(b));
}
__device__ __forceinline__ void unpk2(unsigned long long v, float& lo, float& hi) {
    asm("mov.b64 {%0, %1}, %2;" : "=f"(lo), "=f"(hi) : "l"(v));
}

__device__ __forceinline__ float wsum(float v) {
    #pragma unroll
    for (int o = 16; o > 0; o >>= 1) v += __shfl_xor_sync(0xffffffffu, v, o);
    return v;
}

__device__ __forceinline__ float gelu_exact(float x) {
    return 0.5f * x * (1.0f + erff(x * 0.70710678118654752440f));
}

// ---------------------------------------------------------------------------
// 32x128 @ 128x128 GEMM inside one block (128 threads).
// A is stored TRANSPOSED in shared: A[k][row].
// Thread (cg = lane, rg = warp): cols 4cg..4cg+3, rows 8rg..8rg+7 (4 row pairs).
// acc[rp][c]: .lo = row 8rg+2rp, .hi = row 8rg+2rp+1, col 4cg+c.
// ---------------------------------------------------------------------------
__device__ __forceinline__ void gemm_32x128x128(
    const float (&A)[Dc][34], const float* __restrict__ W,
    float (&Wsl)[16][128], int tid, int cg, int rg,
    unsigned long long (&acc)[4][4])
{
    #pragma unroll
    for (int rp = 0; rp < 4; rp++)
        #pragma unroll
        for (int c = 0; c < 4; c++) acc[rp][c] = 0ull;

    for (int ks = 0; ks < Dc; ks += 16) {
        // stage 16 k-rows of W (16x128 fp32 = 8KB) into shared
        #pragma unroll
        for (int i = 0; i < 4; i++)
            ((float4*)Wsl)[tid + 128 * i] =
                ((const float4*)(W + ks * Dc))[tid + 128 * i];
        __syncthreads();
        #pragma unroll
        for (int kk = 0; kk < 16; kk++) {
            float4 w = *(const float4*)&Wsl[kk][4 * cg];
            unsigned long long bx = pk2(w.x, w.x);
            unsigned long long by = pk2(w.y, w.y);
            unsigned long long bz = pk2(w.z, w.z);
            unsigned long long bw = pk2(w.w, w.w);
            #pragma unroll
            for (int rp = 0; rp < 4; rp++) {
                unsigned long long a2 =
                    *(const unsigned long long*)&A[ks + kk][8 * rg + 2 * rp];
                fma2(acc[rp][0], a2, bx);
                fma2(acc[rp][1], a2, by);
                fma2(acc[rp][2], a2, bz);
                fma2(acc[rp][3], a2, bw);
            }
        }
        __syncthreads();
    }
}

// ---------------------------------------------------------------------------
// Fused kernel: one block per batch. Selection -> gather -> 2x(MLP+LN) -> scatter
// ---------------------------------------------------------------------------
__global__ void __launch_bounds__(128)
scene_graph_kernel(const float* __restrict__ actor_feat,
                   const float* __restrict__ lane_feat,
                   const float* __restrict__ lane_centers,
                   const float* __restrict__ x_centers,
                   const float* __restrict__ spike_rate,
                   const void*  __restrict__ actor_valid_raw,
                   const void*  __restrict__ lane_valid_raw,
                   const float* __restrict__ W0a, const float* __restrict__ b0a,
                   const float* __restrict__ W0b, const float* __restrict__ b0b,
                   const float* __restrict__ W1a, const float* __restrict__ b1a,
                   const float* __restrict__ W1b, const float* __restrict__ b1b,
                   const float* __restrict__ gmm, const float* __restrict__ bta,
                   float* __restrict__ out)
{
    __shared__ float Xs[Dc][34];   // transposed nodes: Xs[k][row]
    __shared__ float Hs[Dc][34];   // transposed hidden
    __shared__ union { float W[16][128]; float ld[NLc]; } u;
    __shared__ float sv[NAc];
    __shared__ int   sel[NNODES];  // [0..15] actor idx, [16..31] lane idx
    __shared__ float ax[KAc], ay[KAc];

    const int tid = threadIdx.x;
    const int b   = blockIdx.x;
    const int cg  = tid & 31;   // lane -> column group (4 cols)
    const int rg  = tid >> 5;   // warp -> row group (8 rows)

    // ---------------- Phase 0: detect boolean encoding ---------------------
    // Inspect this batch's 512 detection bytes of lane_valid:
    //   int32  {0,1}:   only word-offset-0 bytes can be nonzero
    //   float32{0,1.0}: only word-offset 2,3 bytes nonzero (1.0f = 00 00 80 3f)
    //   uint8  random:  word-offset-1 bytes nonzero somewhere (P_miss = 2^-128)
    int enc;  // 0 = uint8, 1 = int32, 2 = float32
    {
        const unsigned char* p = (const unsigned char*)lane_valid_raw + (size_t)b * 512;
        unsigned char b0 = p[tid * 4 + 0];
        unsigned char b1 = p[tid * 4 + 1];
        unsigned char b2 = p[tid * 4 + 2];
        unsigned char b3 = p[tid * 4 + 3];
        int any1   = __syncthreads_or((int)b1);
        int anyOff = __syncthreads_or((int)(b1 | b2 | b3));
        (void)b0;
        enc = anyOff ? (any1 ? 0 : 2) : 1;
    }

    // ---------------- Phase A: actor top-16 (stable, jax top_k tie rule) ----
    {
        bool av;
        if (enc == 0)      av = ((const unsigned char*)actor_valid_raw)[(size_t)b * NAc + tid] != 0;
        else if (enc == 1) av = ((const int*)actor_valid_raw)[(size_t)b * NAc + tid] != 0;
        else               av = ((const float*)actor_valid_raw)[(size_t)b * NAc + tid] != 0.0f;
        float v = spike_rate[b * NAc + tid];
        sv[tid] = av ? v : -INFINITY;
    }
    __syncthreads();
    {
        float mv = sv[tid];
        int cnt = 0;
        #pragma unroll 8
        for (int j = 0; j < NAc; j++) {
            float o = sv[j];
            cnt += (o > mv) || (o == mv && j < tid);
        }
        if (cnt < KAc) sel[cnt] = tid;
    }
    __syncthreads();
    if (tid < KAc) {
        int a = sel[tid];
        ax[tid] = x_centers[((size_t)b * NAc + a) * 2 + 0];
        ay[tid] = x_centers[((size_t)b * NAc + a) * 2 + 1];
    }
    __syncthreads();

    // ---------------- Phase B: lane distances + top-16 smallest ------------
    #pragma unroll
    for (int q = 0; q < 4; q++) {
        int l = tid + 128 * q;
        bool lv;
        if (enc == 0)      lv = ((const unsigned char*)lane_valid_raw)[(size_t)b * NLc + l] != 0;
        else if (enc == 1) lv = ((const int*)lane_valid_raw)[(size_t)b * NLc + l] != 0;
        else               lv = ((const float*)lane_valid_raw)[(size_t)b * NLc + l] != 0.0f;
        float d = INFINITY;
        if (lv) {
            float lx = lane_centers[((size_t)b * NLc + l) * 2 + 0];
            float ly = lane_centers[((size_t)b * NLc + l) * 2 + 1];
            float m = INFINITY;
            #pragma unroll
            for (int a = 0; a < KAc; a++) {
                float dx = __fadd_rn(ax[a], -lx);
                float dy = __fadd_rn(ay[a], -ly);
                float s = __fadd_rn(__fmul_rn(dx, dx), __fmul_rn(dy, dy));
                m = fminf(m, sqrtf(s));
            }
            d = m;
        }
        u.ld[l] = d;
    }
    __syncthreads();
    {
        float dl[4];
        int   cnt[4];
        #pragma unroll
        for (int q = 0; q < 4; q++) { dl[q] = u.ld[tid + 128 * q]; cnt[q] = 0; }
        for (int j = 0; j < NLc; j++) {
            float o = u.ld[j];
            #pragma unroll
            for (int q = 0; q < 4; q++) {
                int l = tid + 128 * q;
                cnt[q] += (o < dl[q]) || (o == dl[q] && j < l);
            }
        }
        #pragma unroll
        for (int q = 0; q < 4; q++)
            if (cnt[q] < KLc) sel[KAc + cnt[q]] = tid + 128 * q;
    }
    __syncthreads();

    // ---------------- Phase C: gather node rows (transposed into Xs) -------
    #pragma unroll 4
    for (int r = 0; r < NNODES; r++) {
        int idx = sel[r];
        const float* src = (r < KAc)
            ? (actor_feat + ((size_t)b * NAc + idx) * Dc)
            : (lane_feat  + ((size_t)b * NLc + idx) * Dc);
        Xs[tid][r] = src[tid];
    }
    __syncthreads();

    // ---------------- Phase D: 2 layers of residual MLP + LayerNorm --------
    float4 g4 = *(const float4*)(gmm + 4 * cg);
    float4 p4 = *(const float4*)(bta + 4 * cg);
    float gar[4] = {g4.x, g4.y, g4.z, g4.w};
    float ber[4] = {p4.x, p4.y, p4.z, p4.w};

    unsigned long long acc[4][4];

    #pragma unroll 1
    for (int layer = 0; layer < 2; layer++) {
        const float* Wa = layer ? W1a : W0a;
        const float* ba = layer ? b1a : b0a;
        const float* Wb = layer ? W1b : W0b;
        const float* bb = layer ? b1b : b0b;

        // ---- GEMM1: H = gelu(X @ Wa + ba), stored transposed in Hs ----
        gemm_32x128x128(Xs, Wa, u.W, tid, cg, rg, acc);
        {
            float4 bq = *(const float4*)(ba + 4 * cg);
            float bar[4] = {bq.x, bq.y, bq.z, bq.w};
            #pragma unroll
            for (int rp = 0; rp < 4; rp++) {
                int row = 8 * rg + 2 * rp;
                #pragma unroll
                for (int c = 0; c < 4; c++) {
                    float lo, hi; unpk2(acc[rp][c], lo, hi);
                    lo = gelu_exact(lo + bar[c]);
                    hi = gelu_exact(hi + bar[c]);
                    Hs[4 * cg + c][row]     = lo;
                    Hs[4 * cg + c][row + 1] = hi;
                }
            }
        }
        __syncthreads();

        // ---- GEMM2: Y = H @ Wb + bb; Z = LN(X + Y) ----
        gemm_32x128x128(Hs, Wb, u.W, tid, cg, rg, acc);
        {
            float4 bq = *(const float4*)(bb + 4 * cg);
            float bbr[4] = {bq.x, bq.y, bq.z, bq.w};
            float zl[4][4], zh[4][4];
            #pragma unroll
            for (int rp = 0; rp < 4; rp++) {
                int row = 8 * rg + 2 * rp;
                float l0[4], h0[4];
                #pragma unroll
                for (int c = 0; c < 4; c++) {
                    float lo, hi; unpk2(acc[rp][c], lo, hi);
                    l0[c] = lo + bbr[c] + Xs[4 * cg + c][row];
                    h0[c] = hi + bbr[c] + Xs[4 * cg + c][row + 1];
                }
                float m_lo = wsum(l0[0] + l0[1] + l0[2] + l0[3]) * 0.0078125f;
                float m_hi = wsum(h0[0] + h0[1] + h0[2] + h0[3]) * 0.0078125f;
                float qlo = 0.f, qhi = 0.f;
                #pragma unroll
                for (int c = 0; c < 4; c++) {
                    float d0 = l0[c] - m_lo; qlo += d0 * d0;
                    float d1 = h0[c] - m_hi; qhi += d1 * d1;
                }
                float v_lo = wsum(qlo) * 0.0078125f;
                float v_hi = wsum(qhi) * 0.0078125f;
                float s_lo = rsqrtf(v_lo + 1e-5f);
                float s_hi = rsqrtf(v_hi + 1e-5f);
                #pragma unroll
                for (int c = 0; c < 4; c++) {
                    zl[rp][c] = (l0[c] - m_lo) * s_lo * gar[c] + ber[c];
                    zh[rp][c] = (h0[c] - m_hi) * s_hi * gar[c] + ber[c];
                }
            }
            __syncthreads();   // all residual reads of Xs complete
            if (layer == 0) {
                #pragma unroll
                for (int rp = 0; rp < 4; rp++) {
                    int row = 8 * rg + 2 * rp;
                    #pragma unroll
                    for (int c = 0; c < 4; c++) {
                        Xs[4 * cg + c][row]     = zl[rp][c];
                        Xs[4 * cg + c][row + 1] = zh[rp][c];
                    }
                }
                __syncthreads();
            } else {
                // ---- Phase E: scatter final rows straight to d_out ----
                const size_t lane_base = (size_t)Bc * NAc * Dc;
                #pragma unroll
                for (int rp = 0; rp < 4; rp++) {
                    int row = 8 * rg + 2 * rp;
                    #pragma unroll
                    for (int h = 0; h < 2; h++) {
                        int r = row + h;
                        int idx = sel[r];
                        size_t base = (r < KAc)
                            ? ((size_t)b * NAc + idx) * Dc
                            : lane_base + ((size_t)b * NLc + idx) * Dc;
                        float4 o;
                        if (h == 0) o = make_float4(zl[rp][0], zl[rp][1], zl[rp][2], zl[rp][3]);
                        else        o = make_float4(zh[rp][0], zh[rp][1], zh[rp][2], zh[rp][3]);
                        *(float4*)(out + base + 4 * cg) = o;
                    }
                }
            }
        }
    }
}

// ---------------------------------------------------------------------------
// kernel_launch: copy pools to out, then fused select/MLP/scatter kernel.
// ---------------------------------------------------------------------------
extern "C" void kernel_launch(void* const* d_in, const int* in_sizes, int n_in,
                              void* d_out, int out_size)
{
    const float* actor_feat   = (const float*)d_in[0];
    const float* lane_feat    = (const float*)d_in[1];
    const float* lane_centers = (const float*)d_in[2];
    const float* x_centers    = (const float*)d_in[3];
    const float* spike_rate   = (const float*)d_in[4];
    const void*  actor_valid  = d_in[5];
    const void*  lane_valid   = d_in[6];
    const float* W0a = (const float*)d_in[7];
    const float* b0a = (const float*)d_in[8];
    const float* W0b = (const float*)d_in[9];
    const float* b0b = (const float*)d_in[10];
    const float* W1a = (const float*)d_in[11];
    const float* b1a = (const float*)d_in[12];
    const float* W1b = (const float*)d_in[13];
    const float* b1b = (const float*)d_in[14];
    const float* gmm = (const float*)d_in[15];
    const float* bta = (const float*)d_in[16];
    float* out = (float*)d_out;

    const size_t actor_elems = (size_t)Bc * NAc * Dc;
    const size_t lane_elems  = (size_t)Bc * NLc * Dc;

    // Base copy of both pools into the output (overwritten rows scattered after)
    cudaMemcpyAsync(out, actor_feat, actor_elems * sizeof(float),
                    cudaMemcpyDeviceToDevice, 0);
    cudaMemcpyAsync(out + actor_elems, lane_feat, lane_elems * sizeof(float),
                    cudaMemcpyDeviceToDevice, 0);

    scene_graph_kernel<<<Bc, 128>>>(actor_feat, lane_feat, lane_centers,
                                    x_centers, spike_rate, actor_valid,
                                    lane_valid,
                                    W0a, b0a, W0b, b0b,
                                    W1a, b1a, W1b, b1b,
                                    gmm, bta, out);
}

// round 3
// speedup vs baseline: 1.1674x; 1.1674x over previous
#include <cuda_runtime.h>
#include <math.h>

// Problem constants
#define Bc   512
#define NAc  128
#define NLc  512
#define Dc   128
#define KAc  16
#define KLc  16
#define NNODES 32   // KA + KL

// Scratch: computed node rows + selection, consumed by scatter kernel.
__device__ float g_nodes[(size_t)Bc * NNODES * Dc];   // 8 MB
__device__ int   g_sel[(size_t)Bc * NNODES];

// ---------------------------------------------------------------------------
// f32x2 helpers (Blackwell packed fp32 FMA)
// ---------------------------------------------------------------------------
__device__ __forceinline__ unsigned long long pk2(float lo, float hi) {
    unsigned long long r;
    asm("mov.b64 %0, {%1, %2};" : "=l"(r) : "f"(lo), "f"(hi));
    return r;
}
__device__ __forceinline__ void fma2(unsigned long long& d,
                                     unsigned long long a,
                                     unsigned long long b) {
    asm("fma.rn.f32x2 %0, %1, %2, %0;" : "+l"(d) : "l"(a), "l"(b));
}
__device__ __forceinline__ void unpk2(unsigned long long v, float& lo, float& hi) {
    asm("mov.b64 {%0, %1}, %2;" : "=f"(lo), "=f"(hi) : "l"(v));
}

__device__ __forceinline__ float wsum(float v) {
    #pragma unroll
    for (int o = 16; o > 0; o >>= 1) v += __shfl_xor_sync(0xffffffffu, v, o);
    return v;
}

__device__ __forceinline__ float gelu_exact(float x) {
    return 0.5f * x * (1.0f + erff(x * 0.70710678118654752440f));
}

// ---------------------------------------------------------------------------
// 32x128 @ 128x128 GEMM, 256 threads (8 warps).
// A transposed in shared: A[k][row]. Warp rg owns rows 4rg..4rg+3 (2 row pairs),
// lane cg owns cols 4cg..4cg+3. acc[rp][c]: .lo=row 4rg+2rp, .hi=row +1.
// ---------------------------------------------------------------------------
__device__ __forceinline__ void gemm_32x128x128(
    const float (&A)[Dc][34], const float* __restrict__ W,
    float (&Wsl)[16][128], int tid, int cg, int rg,
    unsigned long long (&acc)[2][4])
{
    #pragma unroll
    for (int rp = 0; rp < 2; rp++)
        #pragma unroll
        for (int c = 0; c < 4; c++) acc[rp][c] = 0ull;

    for (int ks = 0; ks < Dc; ks += 16) {
        // stage 16 k-rows of W (16x128 fp32 = 8KB): 2 float4 per thread
        #pragma unroll
        for (int i = 0; i < 2; i++)
            ((float4*)Wsl)[tid + 256 * i] =
                ((const float4*)(W + ks * Dc))[tid + 256 * i];
        __syncthreads();
        #pragma unroll
        for (int kk = 0; kk < 16; kk++) {
            float4 w = *(const float4*)&Wsl[kk][4 * cg];
            unsigned long long bx = pk2(w.x, w.x);
            unsigned long long by = pk2(w.y, w.y);
            unsigned long long bz = pk2(w.z, w.z);
            unsigned long long bw = pk2(w.w, w.w);
            #pragma unroll
            for (int rp = 0; rp < 2; rp++) {
                unsigned long long a2 =
                    *(const unsigned long long*)&A[ks + kk][4 * rg + 2 * rp];
                fma2(acc[rp][0], a2, bx);
                fma2(acc[rp][1], a2, by);
                fma2(acc[rp][2], a2, bz);
                fma2(acc[rp][3], a2, bw);
            }
        }
        __syncthreads();
    }
}

// ---------------------------------------------------------------------------
// Compute kernel: selection -> gather -> 2x(MLP+LN) -> write scratch nodes
// ---------------------------------------------------------------------------
__global__ void __launch_bounds__(256)
compute_kernel(const float* __restrict__ actor_feat,
               const float* __restrict__ lane_feat,
               const float* __restrict__ lane_centers,
               const float* __restrict__ x_centers,
               const float* __restrict__ spike_rate,
               const void*  __restrict__ actor_valid_raw,
               const void*  __restrict__ lane_valid_raw,
               const float* __restrict__ W0a, const float* __restrict__ b0a,
               const float* __restrict__ W0b, const float* __restrict__ b0b,
               const float* __restrict__ W1a, const float* __restrict__ b1a,
               const float* __restrict__ W1b, const float* __restrict__ b1b,
               const float* __restrict__ gmm, const float* __restrict__ bta)
{
    __shared__ float Xs[Dc][34];   // transposed nodes: Xs[k][row]
    __shared__ float Hs[Dc][34];   // transposed hidden
    __shared__ union { float W[16][128]; float ld[NLc]; } u;
    __shared__ float sv[NAc];
    __shared__ int   sel[NNODES];
    __shared__ float ax[KAc], ay[KAc];

    const int tid = threadIdx.x;
    const int b   = blockIdx.x;
    const int cg  = tid & 31;   // lane -> column group (4 cols)
    const int rg  = tid >> 5;   // warp -> row group (4 rows)

    // ---------------- Phase 0: detect boolean encoding ---------------------
    //   int32  {0,1}:   only word-offset-0 bytes can be nonzero
    //   float32{0,1.0}: only word-offset 2,3 bytes nonzero (1.0f = 00 00 80 3f)
    //   uint8  random:  word-offset-1 bytes nonzero somewhere
    int enc;  // 0 = uint8, 1 = int32, 2 = float32
    {
        int c1 = 0, cOff = 0;
        if (tid < 128) {
            const unsigned char* p =
                (const unsigned char*)lane_valid_raw + (size_t)b * 512;
            unsigned char b1 = p[tid * 4 + 1];
            unsigned char b2 = p[tid * 4 + 2];
            unsigned char b3 = p[tid * 4 + 3];
            c1 = b1;
            cOff = b1 | b2 | b3;
        }
        int any1   = __syncthreads_or(c1);
        int anyOff = __syncthreads_or(cOff);
        enc = anyOff ? (any1 ? 0 : 2) : 1;
    }

    // ---------------- Phase A: actor top-16 (stable, jax top_k tie rule) ----
    if (tid < NAc) {
        bool av;
        if (enc == 0)      av = ((const unsigned char*)actor_valid_raw)[(size_t)b * NAc + tid] != 0;
        else if (enc == 1) av = ((const int*)actor_valid_raw)[(size_t)b * NAc + tid] != 0;
        else               av = ((const float*)actor_valid_raw)[(size_t)b * NAc + tid] != 0.0f;
        float v = spike_rate[b * NAc + tid];
        sv[tid] = av ? v : -INFINITY;
    }
    __syncthreads();
    if (tid < NAc) {
        float mv = sv[tid];
        int cnt = 0;
        #pragma unroll 8
        for (int j = 0; j < NAc; j++) {
            float o = sv[j];
            cnt += (o > mv) || (o == mv && j < tid);
        }
        if (cnt < KAc) sel[cnt] = tid;
    }
    __syncthreads();
    if (tid < KAc) {
        int a = sel[tid];
        ax[tid] = x_centers[((size_t)b * NAc + a) * 2 + 0];
        ay[tid] = x_centers[((size_t)b * NAc + a) * 2 + 1];
    }
    __syncthreads();

    // ---------------- Phase B: lane distances + top-16 smallest ------------
    #pragma unroll
    for (int q = 0; q < 2; q++) {
        int l = tid + 256 * q;
        bool lv;
        if (enc == 0)      lv = ((const unsigned char*)lane_valid_raw)[(size_t)b * NLc + l] != 0;
        else if (enc == 1) lv = ((const int*)lane_valid_raw)[(size_t)b * NLc + l] != 0;
        else               lv = ((const float*)lane_valid_raw)[(size_t)b * NLc + l] != 0.0f;
        float d = INFINITY;
        if (lv) {
            float lx = lane_centers[((size_t)b * NLc + l) * 2 + 0];
            float ly = lane_centers[((size_t)b * NLc + l) * 2 + 1];
            float m2 = INFINITY;
            #pragma unroll
            for (int a = 0; a < KAc; a++) {
                float dx = __fadd_rn(ax[a], -lx);
                float dy = __fadd_rn(ay[a], -ly);
                float s = __fadd_rn(__fmul_rn(dx, dx), __fmul_rn(dy, dy));
                m2 = fminf(m2, s);
            }
            d = sqrtf(m2);   // sqrt monotone: min(sqrt(s)) == sqrt(min(s))
        }
        u.ld[l] = d;
    }
    __syncthreads();
    {
        float dl[2];
        int   cnt[2];
        #pragma unroll
        for (int q = 0; q < 2; q++) { dl[q] = u.ld[tid + 256 * q]; cnt[q] = 0; }
        #pragma unroll 4
        for (int j = 0; j < NLc; j++) {
            float o = u.ld[j];
            #pragma unroll
            for (int q = 0; q < 2; q++) {
                int l = tid + 256 * q;
                cnt[q] += (o < dl[q]) || (o == dl[q] && j < l);
            }
        }
        #pragma unroll
        for (int q = 0; q < 2; q++)
            if (cnt[q] < KLc) sel[KAc + cnt[q]] = tid + 256 * q;
    }
    __syncthreads();

    // Persist selection for the scatter kernel
    if (tid < NNODES) g_sel[(size_t)b * NNODES + tid] = sel[tid];

    // ---------------- Phase C: gather node rows (transposed into Xs) -------
    {
        int half = tid >> 7;          // 0 -> actor rows, 1 -> lane rows
        int col  = tid & 127;
        #pragma unroll 4
        for (int rr = 0; rr < 16; rr++) {
            int r = rr + (half << 4);
            int idx = sel[r];
            const float* src = half
                ? (lane_feat  + ((size_t)b * NLc + idx) * Dc)
                : (actor_feat + ((size_t)b * NAc + idx) * Dc);
            Xs[col][r] = src[col];
        }
    }
    __syncthreads();

    // ---------------- Phase D: 2 layers of residual MLP + LayerNorm --------
    float4 g4 = *(const float4*)(gmm + 4 * cg);
    float4 p4 = *(const float4*)(bta + 4 * cg);
    float gar[4] = {g4.x, g4.y, g4.z, g4.w};
    float ber[4] = {p4.x, p4.y, p4.z, p4.w};

    unsigned long long acc[2][4];

    #pragma unroll 1
    for (int layer = 0; layer < 2; layer++) {
        const float* Wa = layer ? W1a : W0a;
        const float* ba = layer ? b1a : b0a;
        const float* Wb = layer ? W1b : W0b;
        const float* bb = layer ? b1b : b0b;

        // ---- GEMM1: H = gelu(X @ Wa + ba), stored transposed in Hs ----
        gemm_32x128x128(Xs, Wa, u.W, tid, cg, rg, acc);
        {
            float4 bq = *(const float4*)(ba + 4 * cg);
            float bar[4] = {bq.x, bq.y, bq.z, bq.w};
            #pragma unroll
            for (int rp = 0; rp < 2; rp++) {
                int row = 4 * rg + 2 * rp;
                #pragma unroll
                for (int c = 0; c < 4; c++) {
                    float lo, hi; unpk2(acc[rp][c], lo, hi);
                    lo = gelu_exact(lo + bar[c]);
                    hi = gelu_exact(hi + bar[c]);
                    Hs[4 * cg + c][row]     = lo;
                    Hs[4 * cg + c][row + 1] = hi;
                }
            }
        }
        __syncthreads();

        // ---- GEMM2: Y = H @ Wb + bb; Z = LN(X + Y) ----
        gemm_32x128x128(Hs, Wb, u.W, tid, cg, rg, acc);
        {
            float4 bq = *(const float4*)(bb + 4 * cg);
            float bbr[4] = {bq.x, bq.y, bq.z, bq.w};
            float zl[2][4], zh[2][4];
            #pragma unroll
            for (int rp = 0; rp < 2; rp++) {
                int row = 4 * rg + 2 * rp;
                float l0[4], h0[4];
                #pragma unroll
                for (int c = 0; c < 4; c++) {
                    float lo, hi; unpk2(acc[rp][c], lo, hi);
                    l0[c] = lo + bbr[c] + Xs[4 * cg + c][row];
                    h0[c] = hi + bbr[c] + Xs[4 * cg + c][row + 1];
                }
                float m_lo = wsum(l0[0] + l0[1] + l0[2] + l0[3]) * 0.0078125f;
                float m_hi = wsum(h0[0] + h0[1] + h0[2] + h0[3]) * 0.0078125f;
                float qlo = 0.f, qhi = 0.f;
                #pragma unroll
                for (int c = 0; c < 4; c++) {
                    float d0 = l0[c] - m_lo; qlo += d0 * d0;
                    float d1 = h0[c] - m_hi; qhi += d1 * d1;
                }
                float v_lo = wsum(qlo) * 0.0078125f;
                float v_hi = wsum(qhi) * 0.0078125f;
                float s_lo = rsqrtf(v_lo + 1e-5f);
                float s_hi = rsqrtf(v_hi + 1e-5f);
                #pragma unroll
                for (int c = 0; c < 4; c++) {
                    zl[rp][c] = (l0[c] - m_lo) * s_lo * gar[c] + ber[c];
                    zh[rp][c] = (h0[c] - m_hi) * s_hi * gar[c] + ber[c];
                }
            }
            __syncthreads();   // all residual reads of Xs complete
            if (layer == 0) {
                #pragma unroll
                for (int rp = 0; rp < 2; rp++) {
                    int row = 4 * rg + 2 * rp;
                    #pragma unroll
                    for (int c = 0; c < 4; c++) {
                        Xs[4 * cg + c][row]     = zl[rp][c];
                        Xs[4 * cg + c][row + 1] = zh[rp][c];
                    }
                }
                __syncthreads();
            } else {
                // ---- write final node rows to scratch (float4) ----
                #pragma unroll
                for (int rp = 0; rp < 2; rp++) {
                    int row = 4 * rg + 2 * rp;
                    float4 o0 = make_float4(zl[rp][0], zl[rp][1], zl[rp][2], zl[rp][3]);
                    float4 o1 = make_float4(zh[rp][0], zh[rp][1], zh[rp][2], zh[rp][3]);
                    ((float4*)(g_nodes + ((size_t)b * NNODES + row) * Dc))[cg]     = o0;
                    ((float4*)(g_nodes + ((size_t)b * NNODES + row + 1) * Dc))[cg] = o1;
                }
            }
        }
    }
}

// ---------------------------------------------------------------------------
// Scatter kernel: after pool copy + compute, overwrite selected rows in out.
// ---------------------------------------------------------------------------
__global__ void __launch_bounds__(128)
scatter_kernel(float* __restrict__ out)
{
    const int tid = threadIdx.x;
    const int b   = blockIdx.x;
    const size_t lane_base = (size_t)Bc * NAc * Dc;
    #pragma unroll 4
    for (int r = 0; r < NNODES; r++) {
        int idx = g_sel[(size_t)b * NNODES + r];
        size_t base = (r < KAc)
            ? ((size_t)b * NAc + idx) * Dc
            : lane_base + ((size_t)b * NLc + idx) * Dc;
        out[base + tid] = g_nodes[((size_t)b * NNODES + r) * Dc + tid];
    }
}

// ---------------------------------------------------------------------------
// kernel_launch: fork copy onto a side stream, compute in parallel, join,
// then scatter. All capturable (event fork/join from the legacy stream).
// ---------------------------------------------------------------------------
extern "C" void kernel_launch(void* const* d_in, const int* in_sizes, int n_in,
                              void* d_out, int out_size)
{
    const float* actor_feat   = (const float*)d_in[0];
    const float* lane_feat    = (const float*)d_in[1];
    const float* lane_centers = (const float*)d_in[2];
    const float* x_centers    = (const float*)d_in[3];
    const float* spike_rate   = (const float*)d_in[4];
    const void*  actor_valid  = d_in[5];
    const void*  lane_valid   = d_in[6];
    const float* W0a = (const float*)d_in[7];
    const float* b0a = (const float*)d_in[8];
    const float* W0b = (const float*)d_in[9];
    const float* b0b = (const float*)d_in[10];
    const float* W1a = (const float*)d_in[11];
    const float* b1a = (const float*)d_in[12];
    const float* W1b = (const float*)d_in[13];
    const float* b1b = (const float*)d_in[14];
    const float* gmm = (const float*)d_in[15];
    const float* bta = (const float*)d_in[16];
    float* out = (float*)d_out;

    const size_t actor_elems = (size_t)Bc * NAc * Dc;
    const size_t lane_elems  = (size_t)Bc * NLc * Dc;

    cudaStream_t s2;
    cudaEvent_t eA, eB;
    cudaStreamCreateWithFlags(&s2, cudaStreamNonBlocking);
    cudaEventCreateWithFlags(&eA, cudaEventDisableTiming);
    cudaEventCreateWithFlags(&eB, cudaEventDisableTiming);

    // Fork: side stream does the bulk pool copy into out.
    cudaEventRecord(eA, 0);
    cudaStreamWaitEvent(s2, eA, 0);
    cudaMemcpyAsync(out, actor_feat, actor_elems * sizeof(float),
                    cudaMemcpyDeviceToDevice, s2);
    cudaMemcpyAsync(out + actor_elems, lane_feat, lane_elems * sizeof(float),
                    cudaMemcpyDeviceToDevice, s2);
    cudaEventRecord(eB, s2);

    // Main stream: selection + MLP into scratch (overlaps with the copy).
    compute_kernel<<<Bc, 256>>>(actor_feat, lane_feat, lane_centers,
                                x_centers, spike_rate, actor_valid, lane_valid,
                                W0a, b0a, W0b, b0b,
                                W1a, b1a, W1b, b1b,
                                gmm, bta);

    // Join, then overwrite the 32 selected rows per batch.
    cudaStreamWaitEvent(0, eB, 0);
    scatter_kernel<<<Bc, 128>>>(out);
}